// round 6
// baseline (speedup 1.0000x reference)
#include <cuda_runtime.h>

// ---------------- problem constants ----------------
#define O   130          // output spatial extent per axis
#define P   (O*O)        // 16900, one plane
#define O3  2197000      // 130^3
#define CH  12
// input x is 128^3

// ---------------- scratch (device globals) ----------------
// interleaved layout: g_buf[((z*O + y)*O + w)*12 + c]
__device__ float g_buf[(size_t)O3 * CH];
__device__ float g_partial[10 * 67];
__device__ float g_clip[2];

// shift offsets (oz, oy, ow) for the 6 one-hot dilated stencils, padded coords
__constant__ int c_offs[6][3] = {
    {-1, 1, 1},   // s0: z-minus
    { 1, 1,-1},   // s1: w-minus
    { 1,-1, 1},   // s2: y-minus
    { 1, 1, 3},   // s3: w-plus
    { 3, 1, 1},   // s4: z-plus
    { 1, 3, 1}    // s5: y-plus
};
__constant__ int c_pairs[CH][2] = {
    {1,0},{2,0},{2,1},{3,0},{3,2},{4,1},{4,2},{4,3},{5,0},{5,1},{5,3},{5,4}
};

// ---------------- K1 ----------------
// block = (y-strip of 8, z). Dynamic smem:
//   s_x[3][16][134]  : padded x source planes (jz = z-1, z+1, z+3)
//   s_rs[12][130]    : W-boxed diff^2 rows for current channel
//   s_stage[8*130*12]: interleaved output staging
#define STRIP 8
#define SR    12           // STRIP + 4 halo rows
#define NSTRIP 17          // ceil(130/8)
#define RY    16           // padded-y rows cached: jy in [y0-3, y0+12]
#define SXN   (3*RY*134)   // 6432
#define SRSN  (SR*O)       // 1560
#define STGN  (STRIP*O*CH) // 12480
#define K1_SMEM ((SXN + SRSN + STGN) * 4)

__global__ __launch_bounds__(256) void k1_kernel(const float* __restrict__ x) {
    extern __shared__ float sm[];
    float* s_x     = sm;                 // [3][RY][134]
    float* s_rs    = sm + SXN;           // [SR][O]
    float* s_stage = sm + SXN + SRSN;    // [STRIP][O][CH]

    const int z   = blockIdx.y;
    const int y0  = blockIdx.x * STRIP;
    const int jy0 = y0 - 3;
    const int tid = threadIdx.x;

    // ---- fill 3 padded source planes ----
    for (int idx = tid; idx < SXN; idx += 256) {
        int p   = idx / (RY * 134);
        int rem = idx - p * (RY * 134);
        int ry  = rem / 134;
        int i   = rem - ry * 134;
        int jz = z + 2 * p - 1;          // oz in {-1,1,3}
        int jy = jy0 + ry;
        int jw = i - 1;
        bool ok = (jz >= 0) & (jz <= 131) & (jy >= 0) & (jy <= 131)
                & (jw >= 0) & (jw <= 131);
        int xz = min(max(jz - 2, 0), 127);
        int xy = min(max(jy - 2, 0), 127);
        int xw = min(max(jw - 2, 0), 127);
        float v = 0.0f;
        if (ok) v = __ldg(&x[((size_t)xz << 14) + (xy << 7) + xw]);
        s_x[idx] = v;
    }
    __syncthreads();

    const int nrows = min(STRIP, O - y0);
    const int npair = (nrows + 1) >> 1;

    for (int c = 0; c < CH; c++) {
        const int sa = c_pairs[c][0], sb = c_pairs[c][1];
        const int pa = (c_offs[sa][0] + 1) >> 1, oya = c_offs[sa][1], owa = c_offs[sa][2];
        const int pb = (c_offs[sb][0] + 1) >> 1, oyb = c_offs[sb][1], owb = c_offs[sb][2];

        // ---- W-box of diff^2, two outputs per item ----
        for (int idx = tid; idx < SR * 65; idx += 256) {
            int r  = idx / 65;
            int wp = idx - r * 65;
            int w0 = wp << 1;
            int ay = min(max(y0 - 2 + r, 0), O - 1);
            const float* rowA = s_x + (pa * RY + (ay + oya - jy0)) * 134 + owa + 1;
            const float* rowB = s_x + (pb * RY + (ay + oyb - jy0)) * 134 + owb + 1;
            float t[6];
            #pragma unroll
            for (int k = 0; k < 6; k++) {
                int ww = min(max(w0 - 2 + k, 0), O - 1);
                float d = rowA[ww] - rowB[ww];
                t[k] = d * d;
            }
            s_rs[r * O + w0]     = t[0] + t[1] + t[2] + t[3] + t[4];
            s_rs[r * O + w0 + 1] = t[1] + t[2] + t[3] + t[4] + t[5];
        }
        __syncthreads();

        // ---- H-box, stage interleaved ----
        for (int idx = tid; idx < npair * O; idx += 256) {
            int rp = idx / O;
            int w  = idx - rp * O;
            int ry = rp << 1;
            float a0 = s_rs[ ry      * O + w];
            float a1 = s_rs[(ry + 1) * O + w];
            float a2 = s_rs[(ry + 2) * O + w];
            float a3 = s_rs[(ry + 3) * O + w];
            float a4 = s_rs[(ry + 4) * O + w];
            float o0 = a0 + a1 + a2 + a3 + a4;
            s_stage[(ry * O + w) * CH + c] = o0;
            if (ry + 1 < nrows)
                s_stage[((ry + 1) * O + w) * CH + c] = o0 - a0 + s_rs[(ry + 5) * O + w];
        }
        __syncthreads();
    }

    // ---- coalesced interleaved write: rows y0..y0+nrows-1 of plane z ----
    {
        const float4* st4 = (const float4*)s_stage;
        float4* gb4 = (float4*)g_buf + (size_t)(z * O + y0) * 390;  // O*CH/4 = 390
        const int n4 = nrows * 390;
        for (int idx = tid; idx < n4; idx += 256)
            gb4[idx] = st4[idx];
    }
}

// ---------------- K2: z-box sweep, interleaved float4 reads ----------------
#define ZCH  10
#define ZLEN 13
#define PBLK 67   // ceil(16900/256)

__global__ __launch_bounds__(256) void k2_kernel(float* __restrict__ mind) {
    const int tid = threadIdx.x;
    const int v   = blockIdx.x * 256 + tid;
    const int z0  = blockIdx.y * ZLEN;
    const int z1  = min(z0 + ZLEN, O);
    float acc = 0.0f;

    if (v < P) {
        float sums[CH], w0[CH], w1[CH], w2[CH], w3[CH];
        #pragma unroll
        for (int c = 0; c < CH; c++) sums[c] = 0.0f;

        #pragma unroll
        for (int q = 0; q < 4; q++) {
            int pz = min(max(z0 - 2 + q, 0), O - 1);
            const float4* gp = (const float4*)g_buf + (size_t)(pz * P + v) * 3;
            float4 a = gp[0], b = gp[1], d = gp[2];
            float t[CH] = {a.x,a.y,a.z,a.w, b.x,b.y,b.z,b.w, d.x,d.y,d.z,d.w};
            #pragma unroll
            for (int c = 0; c < CH; c++) {
                sums[c] += t[c];
                if (q == 0) w0[c] = t[c];
                else if (q == 1) w1[c] = t[c];
                else if (q == 2) w2[c] = t[c];
                else w3[c] = t[c];
            }
        }

        for (int z = z0; z < z1; z++) {
            int pz = min(z + 2, O - 1);
            const float4* gp = (const float4*)g_buf + (size_t)(pz * P + v) * 3;
            float4 a = gp[0], b = gp[1], d = gp[2];
            float nv[CH] = {a.x,a.y,a.z,a.w, b.x,b.y,b.z,b.w, d.x,d.y,d.z,d.w};
            #pragma unroll
            for (int c = 0; c < CH; c++) sums[c] += nv[c];

            float mn = sums[0], tot = sums[0];
            #pragma unroll
            for (int c = 1; c < CH; c++) { mn = fminf(mn, sums[c]); tot += sums[c]; }

            #pragma unroll
            for (int c = 0; c < CH; c++)
                mind[(size_t)c * O3 + (size_t)z * P + v] = (sums[c] - mn) * (1.0f / 125.0f);

            acc += (tot * (1.0f / 12.0f) - mn) * (1.0f / 125.0f);

            #pragma unroll
            for (int c = 0; c < CH; c++) {
                sums[c] -= w0[c];
                w0[c] = w1[c]; w1[c] = w2[c]; w2[c] = w3[c]; w3[c] = nv[c];
            }
        }
    }

    __shared__ float red[256];
    red[tid] = acc;
    __syncthreads();
    for (int s = 128; s > 0; s >>= 1) {
        if (tid < s) red[tid] += red[tid + s];
        __syncthreads();
    }
    if (tid == 0) g_partial[blockIdx.y * PBLK + blockIdx.x] = red[0];
}

// ---------------- K2b ----------------
__global__ void k2b_kernel() {
    __shared__ float red[256];
    const int tid = threadIdx.x;
    float a = 0.0f;
    for (int i = tid; i < ZCH * PBLK; i += 256) a += g_partial[i];
    red[tid] = a;
    __syncthreads();
    for (int s = 128; s > 0; s >>= 1) {
        if (tid < s) red[tid] += red[tid + s];
        __syncthreads();
    }
    if (tid == 0) {
        float mean = red[0] / (float)O3;
        g_clip[0] = mean * 0.001f;
        g_clip[1] = mean * 1000.0f;
    }
}

// ---------------- K3: recompute var from channels, exp, float4 ----------------
#define Q4 (O3 / 4)    // 549250

__global__ __launch_bounds__(256) void k3_kernel(float* __restrict__ out) {
    const int v4 = blockIdx.x * 256 + threadIdx.x;
    if (v4 >= Q4) return;
    float4* o4 = (float4*)out;

    float4 m[CH];
    #pragma unroll
    for (int c = 0; c < CH; c++) m[c] = o4[(size_t)c * Q4 + v4];

    float sx = 0.f, sy = 0.f, sz = 0.f, sw = 0.f;
    #pragma unroll
    for (int c = 0; c < CH; c++) {
        sx += m[c].x; sy += m[c].y; sz += m[c].z; sw += m[c].w;
    }
    const float lo = g_clip[0], hi = g_clip[1];
    float ix = 1.0f / fminf(fmaxf(sx * (1.0f/12.0f), lo), hi);
    float iy = 1.0f / fminf(fmaxf(sy * (1.0f/12.0f), lo), hi);
    float iz = 1.0f / fminf(fmaxf(sz * (1.0f/12.0f), lo), hi);
    float iw = 1.0f / fminf(fmaxf(sw * (1.0f/12.0f), lo), hi);

    #pragma unroll
    for (int c = 0; c < CH; c++) {
        float4 r;
        r.x = __expf(-m[c].x * ix);
        r.y = __expf(-m[c].y * iy);
        r.z = __expf(-m[c].z * iz);
        r.w = __expf(-m[c].w * iw);
        o4[(size_t)c * Q4 + v4] = r;
    }
}

// ---------------- launch ----------------
extern "C" void kernel_launch(void* const* d_in, const int* in_sizes, int n_in,
                              void* d_out, int out_size) {
    const float* x = (const float*)d_in[0];
    float* out = (float*)d_out;

    static bool attr_set = false;
    if (!attr_set) {
        cudaFuncSetAttribute(k1_kernel,
                             cudaFuncAttributeMaxDynamicSharedMemorySize, K1_SMEM);
        attr_set = true;
    }

    dim3 g1(NSTRIP, O);
    k1_kernel<<<g1, 256, K1_SMEM>>>(x);

    dim3 g2(PBLK, ZCH);
    k2_kernel<<<g2, 256>>>(out);

    k2b_kernel<<<1, 256>>>();

    k3_kernel<<<(Q4 + 255) / 256, 256>>>(out);
}

// round 7
// speedup vs baseline: 1.2905x; 1.2905x over previous
#include <cuda_runtime.h>

// ---------------- problem constants ----------------
#define O   130          // output spatial extent per axis
#define P   (O*O)        // 16900
#define O3  2197000      // 130^3
#define CH  12
// input x is 128^3

// ---------------- scratch (device globals) ----------------
// channel-pair layout: g_buf2[((pair*O + z)*P + y*O + w)] = {ch 2p, ch 2p+1}
__device__ float2 g_buf2[(size_t)6 * O3];
__device__ float  g_partial[10 * 67];
__device__ float  g_clip[2];

// shift offsets (oz, oy, ow) for the 6 one-hot dilated stencils, padded coords
__constant__ int c_offs[6][3] = {
    {-1, 1, 1},   // s0: z-minus
    { 1, 1,-1},   // s1: w-minus
    { 1,-1, 1},   // s2: y-minus
    { 1, 1, 3},   // s3: w-plus
    { 3, 1, 1},   // s4: z-plus
    { 1, 3, 1}    // s5: y-plus
};
__constant__ int c_pairs[CH][2] = {
    {1,0},{2,0},{2,1},{3,0},{3,2},{4,1},{4,2},{4,3},{5,0},{5,1},{5,3},{5,4}
};

// ---------------- K1: 3 src planes -> pairwise diff^2 -> W-box -> H-box --------
#define STRIP 10
#define SR    14           // STRIP + 4 boxed halo rows
#define NSTRIP 13          // 13*10 = 130
#define RY    18           // padded-y source rows: jy in [y0-3, y0+14]

__global__ __launch_bounds__(256) void k1_kernel(const float* __restrict__ x) {
    __shared__ float s_x[3][RY][134];   // 28.9 KB
    __shared__ float s_r0[SR][O];       // 7.3 KB (channel 2p)
    __shared__ float s_r1[SR][O];       // 7.3 KB (channel 2p+1)

    const int z   = blockIdx.y;
    const int y0  = blockIdx.x * STRIP;
    const int jy0 = y0 - 3;
    const int tid = threadIdx.x;

    // ---- fill 3 padded source planes (jz = z-1, z+1, z+3) ----
    for (int idx = tid; idx < 3 * RY * 134; idx += 256) {
        int p   = idx / (RY * 134);
        int rem = idx - p * (RY * 134);
        int ry  = rem / 134;
        int i   = rem - ry * 134;
        int jz = z + 2 * p - 1;
        int jy = jy0 + ry;
        int jw = i - 1;
        bool ok = (jz >= 0) & (jz <= 131) & (jy >= 0) & (jy <= 131)
                & (jw >= 0) & (jw <= 131);
        int xz = min(max(jz - 2, 0), 127);
        int xy = min(max(jy - 2, 0), 127);
        int xw = min(max(jw - 2, 0), 127);
        float v = 0.0f;
        if (ok) v = __ldg(&x[((size_t)xz << 14) + (xy << 7) + xw]);
        (&s_x[0][0][0])[idx] = v;
    }
    __syncthreads();

    #pragma unroll
    for (int pr = 0; pr < 6; pr++) {
        const int c0 = 2 * pr, c1 = 2 * pr + 1;
        const int sa0 = c_pairs[c0][0], sb0 = c_pairs[c0][1];
        const int sa1 = c_pairs[c1][0], sb1 = c_pairs[c1][1];
        const int pa0 = (c_offs[sa0][0] + 1) >> 1, oya0 = c_offs[sa0][1], owa0 = c_offs[sa0][2];
        const int pb0 = (c_offs[sb0][0] + 1) >> 1, oyb0 = c_offs[sb0][1], owb0 = c_offs[sb0][2];
        const int pa1 = (c_offs[sa1][0] + 1) >> 1, oya1 = c_offs[sa1][1], owa1 = c_offs[sa1][2];
        const int pb1 = (c_offs[sb1][0] + 1) >> 1, oyb1 = c_offs[sb1][1], owb1 = c_offs[sb1][2];

        // ---- W-box of diff^2 for both channels, two outputs per item ----
        for (int idx = tid; idx < SR * 65; idx += 256) {
            int r  = idx / 65;
            int wp = idx - r * 65;
            int w0 = wp << 1;
            int ay = min(max(y0 - 2 + r, 0), O - 1);
            const float* A0 = &s_x[pa0][ay + oya0 - jy0][owa0 + 1];
            const float* B0 = &s_x[pb0][ay + oyb0 - jy0][owb0 + 1];
            const float* A1 = &s_x[pa1][ay + oya1 - jy0][owa1 + 1];
            const float* B1 = &s_x[pb1][ay + oyb1 - jy0][owb1 + 1];
            float t0[6], t1[6];
            #pragma unroll
            for (int k = 0; k < 6; k++) {
                int ww = min(max(w0 - 2 + k, 0), O - 1);
                float d0 = A0[ww] - B0[ww];
                float d1 = A1[ww] - B1[ww];
                t0[k] = d0 * d0;
                t1[k] = d1 * d1;
            }
            s_r0[r][w0]     = t0[0] + t0[1] + t0[2] + t0[3] + t0[4];
            s_r0[r][w0 + 1] = t0[1] + t0[2] + t0[3] + t0[4] + t0[5];
            s_r1[r][w0]     = t1[0] + t1[1] + t1[2] + t1[3] + t1[4];
            s_r1[r][w0 + 1] = t1[1] + t1[2] + t1[3] + t1[4] + t1[5];
        }
        __syncthreads();

        // ---- H-box for both channels, write float2 ----
        float2* gb = &g_buf2[((size_t)pr * O + z) * P + (size_t)y0 * O];
        for (int idx = tid; idx < STRIP * O; idx += 256) {
            int r = idx / O;
            int w = idx - r * O;
            float u0 = s_r0[r][w] + s_r0[r+1][w] + s_r0[r+2][w]
                     + s_r0[r+3][w] + s_r0[r+4][w];
            float u1 = s_r1[r][w] + s_r1[r+1][w] + s_r1[r+2][w]
                     + s_r1[r+3][w] + s_r1[r+4][w];
            gb[idx] = make_float2(u0, u1);
        }
        __syncthreads();
    }
}

// ---------------- K2: z-box sweep over float2 pair streams ----------------
#define ZCH  10
#define ZLEN 13
#define PBLK 67   // ceil(16900/256)

__global__ __launch_bounds__(256) void k2_kernel(float* __restrict__ mind) {
    const int tid = threadIdx.x;
    const int v   = blockIdx.x * 256 + tid;
    const int z0  = blockIdx.y * ZLEN;
    const int z1  = min(z0 + ZLEN, O);
    float acc = 0.0f;

    if (v < P) {
        float sums[CH], w0[CH], w1[CH], w2[CH], w3[CH];
        #pragma unroll
        for (int c = 0; c < CH; c++) sums[c] = 0.0f;

        #pragma unroll
        for (int q = 0; q < 4; q++) {
            int pz = min(max(z0 - 2 + q, 0), O - 1);
            float t[CH];
            #pragma unroll
            for (int pr = 0; pr < 6; pr++) {
                float2 u = g_buf2[((size_t)pr * O + pz) * P + v];
                t[2*pr] = u.x; t[2*pr+1] = u.y;
            }
            #pragma unroll
            for (int c = 0; c < CH; c++) {
                sums[c] += t[c];
                if (q == 0) w0[c] = t[c];
                else if (q == 1) w1[c] = t[c];
                else if (q == 2) w2[c] = t[c];
                else w3[c] = t[c];
            }
        }

        for (int z = z0; z < z1; z++) {
            int pz = min(z + 2, O - 1);
            float nv[CH];
            #pragma unroll
            for (int pr = 0; pr < 6; pr++) {
                float2 u = g_buf2[((size_t)pr * O + pz) * P + v];
                nv[2*pr] = u.x; nv[2*pr+1] = u.y;
            }
            #pragma unroll
            for (int c = 0; c < CH; c++) sums[c] += nv[c];

            float mn = sums[0], tot = sums[0];
            #pragma unroll
            for (int c = 1; c < CH; c++) { mn = fminf(mn, sums[c]); tot += sums[c]; }

            #pragma unroll
            for (int c = 0; c < CH; c++)
                mind[(size_t)c * O3 + (size_t)z * P + v] = (sums[c] - mn) * (1.0f / 125.0f);

            acc += (tot * (1.0f / 12.0f) - mn) * (1.0f / 125.0f);

            #pragma unroll
            for (int c = 0; c < CH; c++) {
                sums[c] -= w0[c];
                w0[c] = w1[c]; w1[c] = w2[c]; w2[c] = w3[c]; w3[c] = nv[c];
            }
        }
    }

    __shared__ float red[256];
    red[tid] = acc;
    __syncthreads();
    for (int s = 128; s > 0; s >>= 1) {
        if (tid < s) red[tid] += red[tid + s];
        __syncthreads();
    }
    if (tid == 0) g_partial[blockIdx.y * PBLK + blockIdx.x] = red[0];
}

// ---------------- K2b: deterministic final reduction -> clip bounds ------------
__global__ void k2b_kernel() {
    __shared__ float red[256];
    const int tid = threadIdx.x;
    float a = 0.0f;
    for (int i = tid; i < ZCH * PBLK; i += 256) a += g_partial[i];
    red[tid] = a;
    __syncthreads();
    for (int s = 128; s > 0; s >>= 1) {
        if (tid < s) red[tid] += red[tid + s];
        __syncthreads();
    }
    if (tid == 0) {
        float mean = red[0] / (float)O3;
        g_clip[0] = mean * 0.001f;
        g_clip[1] = mean * 1000.0f;
    }
}

// ---------------- K3: recompute var from channels, exp, float4 ----------------
#define Q4 (O3 / 4)    // 549250

__global__ __launch_bounds__(256) void k3_kernel(float* __restrict__ out) {
    const int v4 = blockIdx.x * 256 + threadIdx.x;
    if (v4 >= Q4) return;
    float4* o4 = (float4*)out;

    float4 m[CH];
    #pragma unroll
    for (int c = 0; c < CH; c++) m[c] = o4[(size_t)c * Q4 + v4];

    float sx = 0.f, sy = 0.f, sz = 0.f, sw = 0.f;
    #pragma unroll
    for (int c = 0; c < CH; c++) {
        sx += m[c].x; sy += m[c].y; sz += m[c].z; sw += m[c].w;
    }
    const float lo = g_clip[0], hi = g_clip[1];
    float ix = 1.0f / fminf(fmaxf(sx * (1.0f/12.0f), lo), hi);
    float iy = 1.0f / fminf(fmaxf(sy * (1.0f/12.0f), lo), hi);
    float iz = 1.0f / fminf(fmaxf(sz * (1.0f/12.0f), lo), hi);
    float iw = 1.0f / fminf(fmaxf(sw * (1.0f/12.0f), lo), hi);

    #pragma unroll
    for (int c = 0; c < CH; c++) {
        float4 r;
        r.x = __expf(-m[c].x * ix);
        r.y = __expf(-m[c].y * iy);
        r.z = __expf(-m[c].z * iz);
        r.w = __expf(-m[c].w * iw);
        o4[(size_t)c * Q4 + v4] = r;
    }
}

// ---------------- launch ----------------
extern "C" void kernel_launch(void* const* d_in, const int* in_sizes, int n_in,
                              void* d_out, int out_size) {
    const float* x = (const float*)d_in[0];
    float* out = (float*)d_out;

    dim3 g1(NSTRIP, O);
    k1_kernel<<<g1, 256>>>(x);

    dim3 g2(PBLK, ZCH);
    k2_kernel<<<g2, 256>>>(out);

    k2b_kernel<<<1, 256>>>();

    k3_kernel<<<(Q4 + 255) / 256, 256>>>(out);
}